// round 12
// baseline (speedup 1.0000x reference)
#include <cuda_runtime.h>
#include <cuda_bf16.h>
#include <math.h>

#define Kk 32
#define Hh 480
#define Ww 480
#define Nn 576
#define Dd 1024
#define CLSD 64
#define OUTD 256
#define INDIM 1093
#define BK 256
#define NSPLIT 16
#define SLEN 68      // 16*68 = 1088 = Dd+CLSD exactly; geom handled in mlp2
#define GEOM_I 1088  // Dd + CLSD
#define NCHUNK 15    // k_mask row-chunks (32 rows each)

// ---- scratch (static device globals: allocation-free) ----
__device__ int      g_stat15[NCHUNK][BK][8]; // per-chunk partial stats (no init needed)
__device__ float    g_pool[BK * Dd];         // pooled features
__device__ float    g_part[NSPLIT * BK * OUTD];

// ============================================================
// Kernel 1: full-res mask stats. ONE load-round per warp: 8 streaming
// LDG.128/thread in a single batch; parallel 7-thread final reduce.
// grid = (15 chunks of 32 rows, 256 bk) = 3840 blocks, 480 threads.
// ============================================================
__global__ __launch_bounds__(480) void k_mask(const int* __restrict__ masks) {
    const int chunk = blockIdx.x;          // 0..14 (32 rows each)
    const int bk    = blockIdx.y;
    const int tid   = threadIdx.x;
    const int col4  = tid % 120;
    const int rowg  = tid / 120;           // 0..3
    const int h0    = chunk * 32 + rowg;
    const int4* mp  = reinterpret_cast<const int4*>(masks + (size_t)bk * (Hh * Ww))
                      + (size_t)h0 * 120 + col4;

    // single 8-deep load batch (streaming: no L2 pollution, zero reuse)
    int4 v[8];
    #pragma unroll
    for (int t = 0; t < 8; t++)
        v[t] = __ldcs(&mp[(size_t)t * 480]);

    int area = 0, itc = 0, sxo = 0, occ = 0;
    unsigned rocc = 0;
    #pragma unroll
    for (int t = 0; t < 8; t++) {
        int c = v[t].x + v[t].y + v[t].z + v[t].w;
        area += c;
        itc  += c * t;
        sxo  += v[t].y + 2 * v[t].z + 3 * v[t].w;
        occ  |= v[t].x + 2 * v[t].y + 4 * v[t].z + 8 * v[t].w;
        rocc |= ((unsigned)(c + 3) >> 2) << t;      // 1 iff c>=1
    }
    const int w4 = col4 * 4;
    int sx = w4 * area + sxo;
    int sy = h0 * area + 4 * itc;
    int xmn = occ  ? (w4 + __ffs(occ) - 1)         : (1 << 29);
    int xmx = occ  ? (w4 + 31 - __clz(occ))        : -1;
    int ymn = rocc ? (h0 + 4 * (__ffs(rocc) - 1))  : (1 << 29);
    int ymx = rocc ? (h0 + 4 * (31 - __clz(rocc))) : -1;

    #pragma unroll
    for (int off = 16; off; off >>= 1) {
        area += __shfl_down_sync(0xffffffffu, area, off);
        sx   += __shfl_down_sync(0xffffffffu, sx, off);
        sy   += __shfl_down_sync(0xffffffffu, sy, off);
        xmn = min(xmn, __shfl_down_sync(0xffffffffu, xmn, off));
        xmx = max(xmx, __shfl_down_sync(0xffffffffu, xmx, off));
        ymn = min(ymn, __shfl_down_sync(0xffffffffu, ymn, off));
        ymx = max(ymx, __shfl_down_sync(0xffffffffu, ymx, off));
    }
    __shared__ int red7[15][8];
    const int wid = tid >> 5, lid = tid & 31;
    if (lid == 0) {
        int* r = red7[wid];
        r[0] = area; r[1] = sx; r[2] = sy;
        r[3] = xmn; r[4] = xmx; r[5] = ymn; r[6] = ymx;
    }
    __syncthreads();
    // parallel final reduce: one thread per statistic (15 batched LDS each)
    if (tid < 7) {
        int acc = red7[0][tid];
        if (tid < 3) {
            #pragma unroll
            for (int i = 1; i < 15; i++) acc += red7[i][tid];
        } else if (tid == 3 || tid == 5) {
            #pragma unroll
            for (int i = 1; i < 15; i++) acc = min(acc, red7[i][tid]);
        } else {
            #pragma unroll
            for (int i = 1; i < 15; i++) acc = max(acc, red7[i][tid]);
        }
        g_stat15[chunk][bk][tid] = acc;
    }
}

// ============================================================
// Kernel 2: masked pooling, self-contained (samples its own 8 masks inline
// -> no k_init dependency). SMEM-staged fm tiles + 0/1 FFMA multipliers.
// grid = (4 d-chunks, 4 k-groups of 8, 8 b), 256 threads.
// ============================================================
__global__ __launch_bounds__(256) void k_pool(const float* __restrict__ fm,
                                              const int* __restrict__ masks) {
    const int dc  = blockIdx.x;
    const int kg  = blockIdx.y;
    const int b   = blockIdx.z;
    const int tid = threadIdx.x;
    const int d   = dc * 256 + tid;
    const int k0  = kg * 8;

    __shared__ alignas(16) float4 s_m[Nn][2];
    __shared__ alignas(16) float  s_f[24][256];
    __shared__ int   s_cnt8[8];
    __shared__ float s_inv[8];

    if (tid < 8) s_cnt8[tid] = 0;
    __syncthreads();

    // inline sampling of the 24x24 nearest-neighbor grid (src = 20*i, 20*j)
    int cnt[8] = {0, 0, 0, 0, 0, 0, 0, 0};
    for (int n = tid; n < Nn; n += 256) {
        int i = n / 24, jj = n - (n / 24) * 24;
        const int* sp = masks + ((size_t)(b * Kk + k0) * Hh + 20 * i) * Ww + 20 * jj;
        float mk[8];
        #pragma unroll
        for (int kk = 0; kk < 8; kk++) {
            int v = __ldg(sp + (size_t)kk * Hh * Ww);
            mk[kk] = (float)v;
            cnt[kk] += v;
        }
        s_m[n][0] = make_float4(mk[0], mk[1], mk[2], mk[3]);
        s_m[n][1] = make_float4(mk[4], mk[5], mk[6], mk[7]);
    }
    #pragma unroll
    for (int kk = 0; kk < 8; kk++)
        if (cnt[kk]) atomicAdd(&s_cnt8[kk], cnt[kk]);
    __syncthreads();
    if (tid < 8) {
        int c = s_cnt8[tid];
        s_inv[tid] = (c > 0) ? (1.0f / (float)c) : 0.0f;
    }

    float a0 = 0.f, a1 = 0.f, a2 = 0.f, a3 = 0.f;
    float a4 = 0.f, a5 = 0.f, a6 = 0.f, a7 = 0.f;
    const float* fb = fm + (size_t)b * Nn * Dd;
    const int r4 = tid >> 6, c4 = tid & 63;

    for (int n0 = 0; n0 < Nn; n0 += 24) {
        const float4* src = reinterpret_cast<const float4*>(fb + (size_t)n0 * Dd) + dc * 64;
        float4* dst = reinterpret_cast<float4*>(s_f);
        #pragma unroll
        for (int p = 0; p < 6; p++) {
            int r = r4 + p * 4;
            dst[r * 64 + c4] = src[(size_t)r * 256 + c4];
        }
        __syncthreads();
        #pragma unroll 8
        for (int r2 = 0; r2 < 24; r2++) {
            float f = s_f[r2][tid];
            float4 m0 = s_m[n0 + r2][0];
            float4 m1 = s_m[n0 + r2][1];
            a0 = fmaf(f, m0.x, a0); a1 = fmaf(f, m0.y, a1);
            a2 = fmaf(f, m0.z, a2); a3 = fmaf(f, m0.w, a3);
            a4 = fmaf(f, m1.x, a4); a5 = fmaf(f, m1.y, a5);
            a6 = fmaf(f, m1.z, a6); a7 = fmaf(f, m1.w, a7);
        }
        __syncthreads();
    }

    float* pp = g_pool + (size_t)(b * Kk + k0) * Dd + d;
    pp[0 * Dd] = a0 * s_inv[0];
    pp[1 * Dd] = a1 * s_inv[1];
    pp[2 * Dd] = a2 * s_inv[2];
    pp[3 * Dd] = a3 * s_inv[3];
    pp[4 * Dd] = a4 * s_inv[4];
    pp[5 * Dd] = a5 * s_inv[5];
    pp[6 * Dd] = a6 * s_inv[6];
    pp[7 * Dd] = a7 * s_inv[7];
}

// ============================================================
// Kernel 3a: layer1 partial GEMM over i=0..1087 (pooled+cls).
// grid = (16 splits of 68, 32 row-groups of 8), 256 threads.
// Split 15 gathers class embeddings directly (no k_init).
// ============================================================
__global__ __launch_bounds__(256) void k_mlp1(const float* __restrict__ W1,
                                              const void* __restrict__ cls_raw,
                                              const float* __restrict__ emb) {
    const int split = blockIdx.x;
    const int rg    = blockIdx.y;
    const int j     = threadIdx.x;
    const int i0    = split * SLEN;

    __shared__ alignas(16) float xs[8][SLEN + 4];
    __shared__ int s_flag, s_cls[8];

    if (split == NSPLIT - 1) {
        // detect int64 vs int32 class_ids, then gather embedding rows
        if (j == 0) s_flag = 0;
        __syncthreads();
        if (j < 128 && ((const int*)cls_raw)[2 * j + 1] != 0) atomicOr(&s_flag, 1);
        __syncthreads();
        if (j < 8) {
            int row = rg * 8 + j;
            s_cls[j] = (s_flag == 0) ? (int)((const long long*)cls_raw)[row]
                                     : ((const int*)cls_raw)[row];
        }
        __syncthreads();
        #pragma unroll
        for (int r = 0; r < 8; r++) {
            const int row = rg * 8 + r;
            if (j < 4)          xs[r][j] = g_pool[(size_t)row * Dd + i0 + j];
            else if (j < SLEN)  xs[r][j] = emb[(size_t)s_cls[r] * CLSD + (j - 4)];
        }
    } else {
        #pragma unroll
        for (int r = 0; r < 8; r++) {
            if (j < SLEN)
                xs[r][j] = g_pool[(size_t)(rg * 8 + r) * Dd + i0 + j];
        }
    }
    __syncthreads();

    const float* wp = W1 + (size_t)i0 * OUTD + j;
    float a[8];
    #pragma unroll
    for (int r = 0; r < 8; r++) a[r] = 0.f;

    float w[8];
    #pragma unroll
    for (int u = 0; u < 8; u++) w[u] = wp[(size_t)u * OUTD];
    int t = 0;
    for (; t + 16 <= SLEN; t += 8) {
        float wn[8];
        #pragma unroll
        for (int u = 0; u < 8; u++) wn[u] = wp[(size_t)(t + 8 + u) * OUTD];
        #pragma unroll
        for (int r = 0; r < 8; r++) {
            float4 xa = *(const float4*)&xs[r][t];
            float4 xb = *(const float4*)&xs[r][t + 4];
            a[r] = fmaf(xa.x, w[0], a[r]); a[r] = fmaf(xa.y, w[1], a[r]);
            a[r] = fmaf(xa.z, w[2], a[r]); a[r] = fmaf(xa.w, w[3], a[r]);
            a[r] = fmaf(xb.x, w[4], a[r]); a[r] = fmaf(xb.y, w[5], a[r]);
            a[r] = fmaf(xb.z, w[6], a[r]); a[r] = fmaf(xb.w, w[7], a[r]);
        }
        #pragma unroll
        for (int u = 0; u < 8; u++) w[u] = wn[u];
    }
    {   // t = 56..63 (weights already in registers)
        #pragma unroll
        for (int r = 0; r < 8; r++) {
            float4 xa = *(const float4*)&xs[r][t];
            float4 xb = *(const float4*)&xs[r][t + 4];
            a[r] = fmaf(xa.x, w[0], a[r]); a[r] = fmaf(xa.y, w[1], a[r]);
            a[r] = fmaf(xa.z, w[2], a[r]); a[r] = fmaf(xa.w, w[3], a[r]);
            a[r] = fmaf(xb.x, w[4], a[r]); a[r] = fmaf(xb.y, w[5], a[r]);
            a[r] = fmaf(xb.z, w[6], a[r]); a[r] = fmaf(xb.w, w[7], a[r]);
        }
        t += 8;
    }
    for (; t < SLEN; t++) {   // 64..67
        float ws = wp[(size_t)t * OUTD];
        #pragma unroll
        for (int r = 0; r < 8; r++) a[r] = fmaf(xs[r][t], ws, a[r]);
    }

    float* gp = g_part + (size_t)(split * BK + rg * 8) * OUTD + j;
    #pragma unroll
    for (int r = 0; r < 8; r++) gp[(size_t)r * OUTD] = a[r];
}

// ============================================================
// Kernel 3b: combine 16 partials + inline geometry + bias + exact GELU +
// LayerNorm + layer2. grid = 256 blocks (1 row), 256 threads. Only post-join.
// ============================================================
__global__ __launch_bounds__(256) void k_mlp2(const float* __restrict__ b1,
                                              const float* __restrict__ ln_g,
                                              const float* __restrict__ ln_b,
                                              const float* __restrict__ W1,
                                              const float* __restrict__ W2,
                                              const float* __restrict__ b2,
                                              float* __restrict__ out) {
    const int row = blockIdx.x;
    const int j   = threadIdx.x;

    __shared__ alignas(16) float hn[OUTD];
    __shared__ float s_geo[5];
    __shared__ float red[2][8];
    __shared__ float mu_s, is_s;

    // warp 0: reduce the 15 chunk-stat slots -> 5 geometry features
    if (j < 32) {
        int A = 0, SX = 0, SY = 0, xm = 1 << 29, xM = -1, ym = 1 << 29, yM = -1;
        if (j < NCHUNK) {
            const int* st = g_stat15[j][row];
            A = st[0]; SX = st[1]; SY = st[2];
            xm = st[3]; xM = st[4]; ym = st[5]; yM = st[6];
        }
        #pragma unroll
        for (int off = 8; off; off >>= 1) {
            A  += __shfl_down_sync(0xffffffffu, A, off);
            SX += __shfl_down_sync(0xffffffffu, SX, off);
            SY += __shfl_down_sync(0xffffffffu, SY, off);
            xm = min(xm, __shfl_down_sync(0xffffffffu, xm, off));
            xM = max(xM, __shfl_down_sync(0xffffffffu, xM, off));
            ym = min(ym, __shfl_down_sync(0xffffffffu, ym, off));
            yM = max(yM, __shfl_down_sync(0xffffffffu, yM, off));
        }
        if (j == 0) {
            float af = (float)A, safe = fmaxf(af, 1.0f);
            bool valid = (A >= 1);
            s_geo[0] = valid ? (float)SX / safe * (1.0f / Ww) : 0.0f;
            s_geo[1] = valid ? (float)SY / safe * (1.0f / Hh) : 0.0f;
            s_geo[2] = valid ? af * (1.0f / (Hh * Ww)) : 0.0f;
            s_geo[3] = valid ? (float)(xM - xm + 1) * (1.0f / Ww) : 0.0f;
            s_geo[4] = valid ? (float)(yM - ym + 1) * (1.0f / Hh) : 0.0f;
        }
    }

    float v = b1[j];
    #pragma unroll
    for (int s = 0; s < NSPLIT; s++)
        v += g_part[(size_t)(s * BK + row) * OUTD + j];
    __syncthreads();
    #pragma unroll
    for (int g = 0; g < 5; g++)
        v = fmaf(s_geo[g], W1[(size_t)(GEOM_I + g) * OUTD + j], v);
    v = 0.5f * v * (1.0f + erff(v * 0.7071067811865476f));

    float s1 = v, s2 = v * v;
    #pragma unroll
    for (int off = 16; off; off >>= 1) {
        s1 += __shfl_down_sync(0xffffffffu, s1, off);
        s2 += __shfl_down_sync(0xffffffffu, s2, off);
    }
    if ((j & 31) == 0) { red[0][j >> 5] = s1; red[1][j >> 5] = s2; }
    __syncthreads();
    if (j == 0) {
        float a = 0.f, b = 0.f;
        #pragma unroll
        for (int w = 0; w < 8; w++) { a += red[0][w]; b += red[1][w]; }
        float mu  = a * (1.0f / OUTD);
        float var = b * (1.0f / OUTD) - mu * mu;
        mu_s = mu;
        is_s = rsqrtf(var + 1e-5f);
    }
    __syncthreads();
    hn[j] = (v - mu_s) * is_s * ln_g[j] + ln_b[j];
    __syncthreads();

    const float* wp = W2 + j;
    float o0 = b2[j], o1 = 0.f;
    float w[8];
    #pragma unroll
    for (int u = 0; u < 8; u++) w[u] = wp[(size_t)u * OUTD];
    int t = 0;
    for (; t + 16 <= OUTD; t += 8) {
        float wn[8];
        #pragma unroll
        for (int u = 0; u < 8; u++) wn[u] = wp[(size_t)(t + 8 + u) * OUTD];
        float4 ha = *(const float4*)&hn[t];
        float4 hb = *(const float4*)&hn[t + 4];
        o0 = fmaf(ha.x, w[0], o0); o1 = fmaf(ha.y, w[1], o1);
        o0 = fmaf(ha.z, w[2], o0); o1 = fmaf(ha.w, w[3], o1);
        o0 = fmaf(hb.x, w[4], o0); o1 = fmaf(hb.y, w[5], o1);
        o0 = fmaf(hb.z, w[6], o0); o1 = fmaf(hb.w, w[7], o1);
        #pragma unroll
        for (int u = 0; u < 8; u++) w[u] = wn[u];
    }
    {
        float4 ha = *(const float4*)&hn[t];
        float4 hb = *(const float4*)&hn[t + 4];
        o0 = fmaf(ha.x, w[0], o0); o1 = fmaf(ha.y, w[1], o1);
        o0 = fmaf(ha.z, w[2], o0); o1 = fmaf(ha.w, w[3], o1);
        o0 = fmaf(hb.x, w[4], o0); o1 = fmaf(hb.y, w[5], o1);
        o0 = fmaf(hb.z, w[6], o0); o1 = fmaf(hb.w, w[7], o1);
    }
    out[(size_t)row * OUTD + j] = o0 + o1;
}

// ============================================================
extern "C" void kernel_launch(void* const* d_in, const int* in_sizes, int n_in,
                              void* d_out, int out_size) {
    const float* fm    = (const float*)d_in[0];
    const int*   masks = (const int*)d_in[1];
    const void*  cls   = d_in[2];
    const float* emb   = (const float*)d_in[3];
    const float* W1    = (const float*)d_in[4];
    const float* b1    = (const float*)d_in[5];
    const float* lg    = (const float*)d_in[6];
    const float* lb    = (const float*)d_in[7];
    const float* W2    = (const float*)d_in[8];
    const float* b2    = (const float*)d_in[9];
    float* out = (float*)d_out;

    // Fork-join: k_mask (DRAM-bound) on s1 overlaps pool+mlp1.
    cudaStream_t s1 = 0;
    cudaEvent_t  e0 = 0, e1 = 0;
    bool forked =
        (cudaStreamCreateWithFlags(&s1, cudaStreamNonBlocking) == cudaSuccess) &&
        (cudaEventCreateWithFlags(&e0, cudaEventDisableTiming) == cudaSuccess) &&
        (cudaEventCreateWithFlags(&e1, cudaEventDisableTiming) == cudaSuccess);

    if (forked) {
        cudaEventRecord(e0, 0);
        cudaStreamWaitEvent(s1, e0, 0);
        k_mask<<<dim3(NCHUNK, BK), 480, 0, s1>>>(masks);
        cudaEventRecord(e1, s1);

        k_pool<<<dim3(4, 4, 8), 256>>>(fm, masks);
        k_mlp1<<<dim3(NSPLIT, 32), 256>>>(W1, cls, emb);

        cudaStreamWaitEvent(0, e1, 0);       // join: only mlp2 needs mask stats
        k_mlp2<<<BK, 256>>>(b1, lg, lb, W1, W2, b2, out);
    } else {
        k_mask<<<dim3(NCHUNK, BK), 480>>>(masks);
        k_pool<<<dim3(4, 4, 8), 256>>>(fm, masks);
        k_mlp1<<<dim3(NSPLIT, 32), 256>>>(W1, cls, emb);
        k_mlp2<<<BK, 256>>>(b1, lg, lb, W1, W2, b2, out);
    }

    if (e0) cudaEventDestroy(e0);
    if (e1) cudaEventDestroy(e1);
    if (s1) cudaStreamDestroy(s1);
}

// round 14
// speedup vs baseline: 2.0359x; 2.0359x over previous
#include <cuda_runtime.h>
#include <cuda_bf16.h>
#include <math.h>

#define Kk 32
#define Hh 480
#define Ww 480
#define Nn 576
#define Dd 1024
#define CLSD 64
#define OUTD 256
#define INDIM 1093
#define BK 256
#define XS 1096      // padded row stride of assembled x
#define NSPLIT 16
#define SLEN 68      // 16*68 = 1088 = Dd+CLSD exactly; geom handled in mlp2
#define GEOM_I 1088  // Dd + CLSD
#define NCHUNK 15    // k_mask row-chunks (32 rows each)

// ---- scratch (static device globals: allocation-free) ----
__device__ int      g_stat15[NCHUNK][BK][8]; // per-chunk partial stats (no init needed)
__device__ unsigned g_bits[BK * 18];         // 576-bit sample mask per (b,k)
__device__ int      g_cnt[BK];
__device__ float    g_x[BK * XS];            // assembled [pooled | cls]
__device__ float    g_part[NSPLIT * BK * OUTD];

// ============================================================
// Kernel 0: sample bits + class-embedding gather (the ONE scattered pass).
// grid = 256 (one per b,k), 576 threads (24x24 sample grid).
// ============================================================
__global__ __launch_bounds__(576) void k_init(const int* __restrict__ masks,
                                              const void* __restrict__ cls_raw,
                                              const float* __restrict__ emb) {
    const int bk  = blockIdx.x;
    const int tid = threadIdx.x;
    const int wid = tid >> 5, lid = tid & 31;
    __shared__ int s_flag, s_cnt;
    if (tid == 0) { s_flag = 0; s_cnt = 0; }
    __syncthreads();
    // detect int64 vs int32 class_ids (odd 32-bit words all zero => int64)
    if (tid < 128) {
        if (((const int*)cls_raw)[2 * tid + 1] != 0) atomicOr(&s_flag, 1);
    }
    // sampled 24x24 bits (nearest: src = 20*i, 20*j)
    const int* mb = masks + (size_t)bk * (Hh * Ww);
    int i = tid / 24, j = tid - i * 24;
    int on = mb[(20 * i) * Ww + 20 * j] > 0;
    unsigned bal = __ballot_sync(0xffffffffu, on);
    if (lid == 0) { g_bits[bk * 18 + wid] = bal; atomicAdd(&s_cnt, __popc(bal)); }
    __syncthreads();
    if (tid == 0) g_cnt[bk] = s_cnt;
    const bool is64 = (s_flag == 0);
    int c = is64 ? (int)((const long long*)cls_raw)[bk]
                 : ((const int*)cls_raw)[bk];
    if (tid < CLSD) g_x[(size_t)bk * XS + Dd + tid] = emb[c * CLSD + tid];
}

// ============================================================
// Kernel 1: full-res mask stats. ONE load-round per warp: 8 streaming
// LDG.128/thread in a single batch; parallel 7-thread final reduce.
// grid = (15 chunks of 32 rows, 256 bk) = 3840 blocks, 480 threads.
// ============================================================
__global__ __launch_bounds__(480) void k_mask(const int* __restrict__ masks) {
    const int chunk = blockIdx.x;          // 0..14 (32 rows each)
    const int bk    = blockIdx.y;
    const int tid   = threadIdx.x;
    const int col4  = tid % 120;
    const int rowg  = tid / 120;           // 0..3
    const int h0    = chunk * 32 + rowg;
    const int4* mp  = reinterpret_cast<const int4*>(masks + (size_t)bk * (Hh * Ww))
                      + (size_t)h0 * 120 + col4;

    // single 8-deep load batch (streaming: no L2 pollution, zero reuse)
    int4 v[8];
    #pragma unroll
    for (int t = 0; t < 8; t++)
        v[t] = __ldcs(&mp[(size_t)t * 480]);

    int area = 0, itc = 0, sxo = 0, occ = 0;
    unsigned rocc = 0;
    #pragma unroll
    for (int t = 0; t < 8; t++) {
        int c = v[t].x + v[t].y + v[t].z + v[t].w;
        area += c;
        itc  += c * t;
        sxo  += v[t].y + 2 * v[t].z + 3 * v[t].w;
        occ  |= v[t].x + 2 * v[t].y + 4 * v[t].z + 8 * v[t].w;
        rocc |= ((unsigned)(c + 3) >> 2) << t;      // 1 iff c>=1
    }
    const int w4 = col4 * 4;
    int sx = w4 * area + sxo;
    int sy = h0 * area + 4 * itc;
    int xmn = occ  ? (w4 + __ffs(occ) - 1)         : (1 << 29);
    int xmx = occ  ? (w4 + 31 - __clz(occ))        : -1;
    int ymn = rocc ? (h0 + 4 * (__ffs(rocc) - 1))  : (1 << 29);
    int ymx = rocc ? (h0 + 4 * (31 - __clz(rocc))) : -1;

    #pragma unroll
    for (int off = 16; off; off >>= 1) {
        area += __shfl_down_sync(0xffffffffu, area, off);
        sx   += __shfl_down_sync(0xffffffffu, sx, off);
        sy   += __shfl_down_sync(0xffffffffu, sy, off);
        xmn = min(xmn, __shfl_down_sync(0xffffffffu, xmn, off));
        xmx = max(xmx, __shfl_down_sync(0xffffffffu, xmx, off));
        ymn = min(ymn, __shfl_down_sync(0xffffffffu, ymn, off));
        ymx = max(ymx, __shfl_down_sync(0xffffffffu, ymx, off));
    }
    __shared__ int red7[15][8];
    const int wid = tid >> 5, lid = tid & 31;
    if (lid == 0) {
        int* r = red7[wid];
        r[0] = area; r[1] = sx; r[2] = sy;
        r[3] = xmn; r[4] = xmx; r[5] = ymn; r[6] = ymx;
    }
    __syncthreads();
    // parallel final reduce: one thread per statistic (15 batched LDS each)
    if (tid < 7) {
        int acc = red7[0][tid];
        if (tid < 3) {
            #pragma unroll
            for (int i = 1; i < 15; i++) acc += red7[i][tid];
        } else if (tid == 3 || tid == 5) {
            #pragma unroll
            for (int i = 1; i < 15; i++) acc = min(acc, red7[i][tid]);
        } else {
            #pragma unroll
            for (int i = 1; i < 15; i++) acc = max(acc, red7[i][tid]);
        }
        g_stat15[chunk][bk][tid] = acc;
    }
}

// ============================================================
// Kernel 2: masked pooling via SMEM-staged fm tiles + 0/1 multipliers.
// grid = (4 d-chunks, 4 k-groups of 8, 8 b), 256 threads.
// ============================================================
__global__ __launch_bounds__(256) void k_pool(const float* __restrict__ fm) {
    const int dc  = blockIdx.x;
    const int kg  = blockIdx.y;
    const int b   = blockIdx.z;
    const int tid = threadIdx.x;
    const int d   = dc * 256 + tid;
    const int k0  = kg * 8;

    __shared__ alignas(16) float4 s_m[Nn][2];
    __shared__ alignas(16) float  s_f[24][256];
    __shared__ float s_inv[8];

    for (int n = tid; n < Nn; n += 256) {
        float mk[8];
        #pragma unroll
        for (int kk = 0; kk < 8; kk++) {
            unsigned word = g_bits[(b * Kk + k0 + kk) * 18 + (n >> 5)];
            mk[kk] = ((word >> (n & 31)) & 1u) ? 1.0f : 0.0f;
        }
        s_m[n][0] = make_float4(mk[0], mk[1], mk[2], mk[3]);
        s_m[n][1] = make_float4(mk[4], mk[5], mk[6], mk[7]);
    }
    if (tid < 8) {
        int c = g_cnt[b * Kk + k0 + tid];
        s_inv[tid] = (c > 0) ? (1.0f / (float)c) : 0.0f;
    }
    __syncthreads();

    float a0 = 0.f, a1 = 0.f, a2 = 0.f, a3 = 0.f;
    float a4 = 0.f, a5 = 0.f, a6 = 0.f, a7 = 0.f;
    const float* fb = fm + (size_t)b * Nn * Dd;
    const int r4 = tid >> 6, c4 = tid & 63;

    for (int n0 = 0; n0 < Nn; n0 += 24) {
        const float4* src = reinterpret_cast<const float4*>(fb + (size_t)n0 * Dd) + dc * 64;
        float4* dst = reinterpret_cast<float4*>(s_f);
        #pragma unroll
        for (int p = 0; p < 6; p++) {
            int r = r4 + p * 4;
            dst[r * 64 + c4] = src[(size_t)r * 256 + c4];
        }
        __syncthreads();
        #pragma unroll 8
        for (int r2 = 0; r2 < 24; r2++) {
            float f = s_f[r2][tid];
            float4 m0 = s_m[n0 + r2][0];
            float4 m1 = s_m[n0 + r2][1];
            a0 = fmaf(f, m0.x, a0); a1 = fmaf(f, m0.y, a1);
            a2 = fmaf(f, m0.z, a2); a3 = fmaf(f, m0.w, a3);
            a4 = fmaf(f, m1.x, a4); a5 = fmaf(f, m1.y, a5);
            a6 = fmaf(f, m1.z, a6); a7 = fmaf(f, m1.w, a7);
        }
        __syncthreads();
    }

    float* pp = g_x + (size_t)(b * Kk + k0) * XS + d;
    pp[0 * XS] = a0 * s_inv[0];
    pp[1 * XS] = a1 * s_inv[1];
    pp[2 * XS] = a2 * s_inv[2];
    pp[3 * XS] = a3 * s_inv[3];
    pp[4 * XS] = a4 * s_inv[4];
    pp[5 * XS] = a5 * s_inv[5];
    pp[6 * XS] = a6 * s_inv[6];
    pp[7 * XS] = a7 * s_inv[7];
}

// ============================================================
// Kernel 3a: layer1 partial GEMM over i=0..1087 (pooled+cls only).
// grid = (16 splits of 68, 32 row-groups of 8) = 512 blocks, 256 threads.
// Entirely pre-join: depends only on k_init + k_pool.
// ============================================================
__global__ __launch_bounds__(256) void k_mlp1(const float* __restrict__ W1) {
    const int split = blockIdx.x;
    const int rg    = blockIdx.y;
    const int j     = threadIdx.x;
    const int i0    = split * SLEN;

    __shared__ alignas(16) float xs[8][SLEN + 4];

    #pragma unroll
    for (int r = 0; r < 8; r++) {
        if (j < SLEN) xs[r][j] = g_x[(size_t)(rg * 8 + r) * XS + i0 + j];
    }
    __syncthreads();

    const float* wp = W1 + (size_t)i0 * OUTD + j;
    float a[8];
    #pragma unroll
    for (int r = 0; r < 8; r++) a[r] = 0.f;

    float w[8];
    #pragma unroll
    for (int u = 0; u < 8; u++) w[u] = wp[(size_t)u * OUTD];
    int t = 0;
    for (; t + 16 <= SLEN; t += 8) {
        float wn[8];
        #pragma unroll
        for (int u = 0; u < 8; u++) wn[u] = wp[(size_t)(t + 8 + u) * OUTD];
        #pragma unroll
        for (int r = 0; r < 8; r++) {
            float4 xa = *(const float4*)&xs[r][t];
            float4 xb = *(const float4*)&xs[r][t + 4];
            a[r] = fmaf(xa.x, w[0], a[r]); a[r] = fmaf(xa.y, w[1], a[r]);
            a[r] = fmaf(xa.z, w[2], a[r]); a[r] = fmaf(xa.w, w[3], a[r]);
            a[r] = fmaf(xb.x, w[4], a[r]); a[r] = fmaf(xb.y, w[5], a[r]);
            a[r] = fmaf(xb.z, w[6], a[r]); a[r] = fmaf(xb.w, w[7], a[r]);
        }
        #pragma unroll
        for (int u = 0; u < 8; u++) w[u] = wn[u];
    }
    {   // t = 56..63 (weights already in registers)
        #pragma unroll
        for (int r = 0; r < 8; r++) {
            float4 xa = *(const float4*)&xs[r][t];
            float4 xb = *(const float4*)&xs[r][t + 4];
            a[r] = fmaf(xa.x, w[0], a[r]); a[r] = fmaf(xa.y, w[1], a[r]);
            a[r] = fmaf(xa.z, w[2], a[r]); a[r] = fmaf(xa.w, w[3], a[r]);
            a[r] = fmaf(xb.x, w[4], a[r]); a[r] = fmaf(xb.y, w[5], a[r]);
            a[r] = fmaf(xb.z, w[6], a[r]); a[r] = fmaf(xb.w, w[7], a[r]);
        }
        t += 8;
    }
    for (; t < SLEN; t++) {   // 64..67
        float ws = wp[(size_t)t * OUTD];
        #pragma unroll
        for (int r = 0; r < 8; r++) a[r] = fmaf(xs[r][t], ws, a[r]);
    }

    float* gp = g_part + (size_t)(split * BK + rg * 8) * OUTD + j;
    #pragma unroll
    for (int r = 0; r < 8; r++) gp[(size_t)r * OUTD] = a[r];
}

// ============================================================
// Kernel 3b: combine 16 partials + inline geometry + bias + exact GELU +
// LayerNorm + layer2 with SPLIT-I halves (512 threads: tid<256 -> i[0,128),
// tid>=256 -> i[128,256) of the same output column). Only post-join kernel.
// ============================================================
__global__ __launch_bounds__(512) void k_mlp2(const float* __restrict__ b1,
                                              const float* __restrict__ ln_g,
                                              const float* __restrict__ ln_b,
                                              const float* __restrict__ W1,
                                              const float* __restrict__ W2,
                                              const float* __restrict__ b2,
                                              float* __restrict__ out) {
    const int row  = blockIdx.x;
    const int tid  = threadIdx.x;
    const int j    = tid & 255;
    const int half = tid >> 8;

    __shared__ alignas(16) float hn[OUTD];
    __shared__ float s_geo[5];
    __shared__ float red[2][8];
    __shared__ float mu_s, is_s;
    __shared__ float o_part[OUTD];

    // warp 0: reduce the 15 chunk-stat slots -> 5 geometry features
    if (tid < 32) {
        int A = 0, SX = 0, SY = 0, xm = 1 << 29, xM = -1, ym = 1 << 29, yM = -1;
        if (tid < NCHUNK) {
            const int* st = g_stat15[tid][row];
            A = st[0]; SX = st[1]; SY = st[2];
            xm = st[3]; xM = st[4]; ym = st[5]; yM = st[6];
        }
        #pragma unroll
        for (int off = 8; off; off >>= 1) {
            A  += __shfl_down_sync(0xffffffffu, A, off);
            SX += __shfl_down_sync(0xffffffffu, SX, off);
            SY += __shfl_down_sync(0xffffffffu, SY, off);
            xm = min(xm, __shfl_down_sync(0xffffffffu, xm, off));
            xM = max(xM, __shfl_down_sync(0xffffffffu, xM, off));
            ym = min(ym, __shfl_down_sync(0xffffffffu, ym, off));
            yM = max(yM, __shfl_down_sync(0xffffffffu, yM, off));
        }
        if (tid == 0) {
            float af = (float)A, safe = fmaxf(af, 1.0f);
            bool valid = (A >= 1);
            s_geo[0] = valid ? (float)SX / safe * (1.0f / Ww) : 0.0f;
            s_geo[1] = valid ? (float)SY / safe * (1.0f / Hh) : 0.0f;
            s_geo[2] = valid ? af * (1.0f / (Hh * Ww)) : 0.0f;
            s_geo[3] = valid ? (float)(xM - xm + 1) * (1.0f / Ww) : 0.0f;
            s_geo[4] = valid ? (float)(yM - ym + 1) * (1.0f / Hh) : 0.0f;
        }
    }

    float v = 0.f;
    if (half == 0) {
        v = b1[j];
        #pragma unroll
        for (int s = 0; s < NSPLIT; s++)
            v += g_part[(size_t)(s * BK + row) * OUTD + j];
    }
    __syncthreads();
    if (half == 0) {
        #pragma unroll
        for (int g = 0; g < 5; g++)
            v = fmaf(s_geo[g], W1[(size_t)(GEOM_I + g) * OUTD + j], v);
        v = 0.5f * v * (1.0f + erff(v * 0.7071067811865476f));
        float s1 = v, s2 = v * v;
        #pragma unroll
        for (int off = 16; off; off >>= 1) {
            s1 += __shfl_down_sync(0xffffffffu, s1, off);
            s2 += __shfl_down_sync(0xffffffffu, s2, off);
        }
        if ((j & 31) == 0) { red[0][j >> 5] = s1; red[1][j >> 5] = s2; }
    }
    __syncthreads();
    if (tid == 0) {
        float a = 0.f, b = 0.f;
        #pragma unroll
        for (int w = 0; w < 8; w++) { a += red[0][w]; b += red[1][w]; }
        float mu  = a * (1.0f / OUTD);
        float var = b * (1.0f / OUTD) - mu * mu;
        mu_s = mu;
        is_s = rsqrtf(var + 1e-5f);
    }
    __syncthreads();
    if (half == 0)
        hn[j] = (v - mu_s) * is_s * ln_g[j] + ln_b[j];
    __syncthreads();

    // layer2 split-i: each half does 128 of the 256 i's for column j
    const int ibase = half * 128;
    const float* wp = W2 + (size_t)ibase * OUTD + j;
    float o0 = (half == 0) ? b2[j] : 0.f, o1 = 0.f;
    float w[8];
    #pragma unroll
    for (int u = 0; u < 8; u++) w[u] = wp[(size_t)u * OUTD];
    int t = 0;
    for (; t + 16 <= 128; t += 8) {
        float wn[8];
        #pragma unroll
        for (int u = 0; u < 8; u++) wn[u] = wp[(size_t)(t + 8 + u) * OUTD];
        float4 ha = *(const float4*)&hn[ibase + t];
        float4 hb = *(const float4*)&hn[ibase + t + 4];
        o0 = fmaf(ha.x, w[0], o0); o1 = fmaf(ha.y, w[1], o1);
        o0 = fmaf(ha.z, w[2], o0); o1 = fmaf(ha.w, w[3], o1);
        o0 = fmaf(hb.x, w[4], o0); o1 = fmaf(hb.y, w[5], o1);
        o0 = fmaf(hb.z, w[6], o0); o1 = fmaf(hb.w, w[7], o1);
        #pragma unroll
        for (int u = 0; u < 8; u++) w[u] = wn[u];
    }
    {   // final 8 (weights in registers)
        float4 ha = *(const float4*)&hn[ibase + t];
        float4 hb = *(const float4*)&hn[ibase + t + 4];
        o0 = fmaf(ha.x, w[0], o0); o1 = fmaf(ha.y, w[1], o1);
        o0 = fmaf(ha.z, w[2], o0); o1 = fmaf(ha.w, w[3], o1);
        o0 = fmaf(hb.x, w[4], o0); o1 = fmaf(hb.y, w[5], o1);
        o0 = fmaf(hb.z, w[6], o0); o1 = fmaf(hb.w, w[7], o1);
    }
    if (half == 1) o_part[j] = o0 + o1;
    __syncthreads();
    if (half == 0)
        out[(size_t)row * OUTD + j] = o0 + o1 + o_part[j];
}

// ============================================================
extern "C" void kernel_launch(void* const* d_in, const int* in_sizes, int n_in,
                              void* d_out, int out_size) {
    const float* fm    = (const float*)d_in[0];
    const int*   masks = (const int*)d_in[1];
    const void*  cls   = d_in[2];
    const float* emb   = (const float*)d_in[3];
    const float* W1    = (const float*)d_in[4];
    const float* b1    = (const float*)d_in[5];
    const float* lg    = (const float*)d_in[6];
    const float* lb    = (const float*)d_in[7];
    const float* W2    = (const float*)d_in[8];
    const float* b2    = (const float*)d_in[9];
    float* out = (float*)d_out;

    // Fork-join: k_mask (DRAM-bound) on s1 overlaps init+pool+ALL of mlp1.
    cudaStream_t s1 = 0;
    cudaEvent_t  e0 = 0, e1 = 0;
    bool forked =
        (cudaStreamCreateWithFlags(&s1, cudaStreamNonBlocking) == cudaSuccess) &&
        (cudaEventCreateWithFlags(&e0, cudaEventDisableTiming) == cudaSuccess) &&
        (cudaEventCreateWithFlags(&e1, cudaEventDisableTiming) == cudaSuccess);

    if (forked) {
        cudaEventRecord(e0, 0);
        cudaStreamWaitEvent(s1, e0, 0);
        k_mask<<<dim3(NCHUNK, BK), 480, 0, s1>>>(masks);
        cudaEventRecord(e1, s1);

        k_init<<<BK, 576>>>(masks, cls, emb);
        k_pool<<<dim3(4, 4, 8), 256>>>(fm);
        k_mlp1<<<dim3(NSPLIT, 32), 256>>>(W1);

        cudaStreamWaitEvent(0, e1, 0);       // join: only mlp2 needs mask stats
        k_mlp2<<<BK, 512>>>(b1, lg, lb, W1, W2, b2, out);
    } else {
        k_init<<<BK, 576>>>(masks, cls, emb);
        k_mask<<<dim3(NCHUNK, BK), 480>>>(masks);
        k_pool<<<dim3(4, 4, 8), 256>>>(fm);
        k_mlp1<<<dim3(NSPLIT, 32), 256>>>(W1);
        k_mlp2<<<BK, 512>>>(b1, lg, lb, W1, W2, b2, out);
    }

    if (e0) cudaEventDestroy(e0);
    if (e1) cudaEventDestroy(e1);
    if (s1) cudaStreamDestroy(s1);
}

// round 16
// speedup vs baseline: 2.0663x; 1.0150x over previous
#include <cuda_runtime.h>
#include <cuda_bf16.h>
#include <math.h>

#define Kk 32
#define Hh 480
#define Ww 480
#define Nn 576
#define Dd 1024
#define CLSD 64
#define OUTD 256
#define INDIM 1093
#define BK 256
#define XS 1096      // padded row stride of assembled x
#define NSPLIT 16
#define SLEN 68      // 16*68 = 1088 = Dd+CLSD exactly; geom handled in mlp2
#define GEOM_I 1088  // Dd + CLSD
#define NCHUNK 25    // k_mask chunks per image (2304 int4 each)
#define CHUNK_I4 2304

// ---- scratch (static device globals: allocation-free) ----
__device__ int      g_stat25[NCHUNK][BK][8]; // per-chunk partial stats (no init needed)
__device__ unsigned g_bits[BK * 18];         // 576-bit sample mask per (b,k)
__device__ int      g_cnt[BK];
__device__ float    g_x[BK * XS];            // assembled [pooled | cls]
__device__ float    g_part[NSPLIT * BK * OUTD];

// ============================================================
// Kernel 0: sample bits + class-embedding gather (the ONE scattered pass).
// grid = 256 (one per b,k), 576 threads (24x24 sample grid).
// ============================================================
__global__ __launch_bounds__(576) void k_init(const int* __restrict__ masks,
                                              const void* __restrict__ cls_raw,
                                              const float* __restrict__ emb) {
    const int bk  = blockIdx.x;
    const int tid = threadIdx.x;
    const int wid = tid >> 5, lid = tid & 31;
    __shared__ int s_flag, s_cnt;
    if (tid == 0) { s_flag = 0; s_cnt = 0; }
    __syncthreads();
    // detect int64 vs int32 class_ids (odd 32-bit words all zero => int64)
    if (tid < 128) {
        if (((const int*)cls_raw)[2 * tid + 1] != 0) atomicOr(&s_flag, 1);
    }
    // sampled 24x24 bits (nearest: src = 20*i, 20*j)
    const int* mb = masks + (size_t)bk * (Hh * Ww);
    int i = tid / 24, j = tid - i * 24;
    int on = mb[(20 * i) * Ww + 20 * j] > 0;
    unsigned bal = __ballot_sync(0xffffffffu, on);
    if (lid == 0) { g_bits[bk * 18 + wid] = bal; atomicAdd(&s_cnt, __popc(bal)); }
    __syncthreads();
    if (tid == 0) g_cnt[bk] = s_cnt;
    const bool is64 = (s_flag == 0);
    int c = is64 ? (int)((const long long*)cls_raw)[bk]
                 : ((const int*)cls_raw)[bk];
    if (tid < CLSD) g_x[(size_t)bk * XS + Dd + tid] = emb[c * CLSD + tid];
}

// ============================================================
// Kernel 1 (v3): full-res mask stats. 256-thread blocks, 9 coalesced
// streaming int4 loads/thread in ONE batch -> 4 blocks/SM = 4 independent
// load streams, small 8-warp reduce tails. grid = (25 chunks, 256 bk).
// ============================================================
__global__ __launch_bounds__(256) void k_mask(const int* __restrict__ masks) {
    const int chunk = blockIdx.x;          // 0..24 (2304 int4 each)
    const int bk    = blockIdx.y;
    const int tid   = threadIdx.x;
    const int4* mp  = reinterpret_cast<const int4*>(masks + (size_t)bk * (Hh * Ww));
    const int base  = chunk * CHUNK_I4 + tid;

    // single 9-deep coalesced load batch (streaming: zero reuse)
    int4 v[9];
    #pragma unroll
    for (int u = 0; u < 9; u++)
        v[u] = __ldcs(&mp[base + u * 256]);

    int area = 0, sx = 0, sy = 0;
    int xmn = 1 << 29, xmx = -1, ymn = 1 << 29, ymx = -1;
    #pragma unroll
    for (int u = 0; u < 9; u++) {
        const int gidx = base + u * 256;
        const int h    = gidx / 120;               // magic-multiply
        const int w4   = (gidx - h * 120) * 4;
        int c = v[u].x + v[u].y + v[u].z + v[u].w;
        area += c;
        sy   += h * c;
        sx   += w4 * c + v[u].y + 2 * v[u].z + 3 * v[u].w;
        int occ4 = v[u].x + 2 * v[u].y + 4 * v[u].z + 8 * v[u].w;
        if (occ4) {
            xmn = min(xmn, w4 + __ffs(occ4) - 1);
            xmx = max(xmx, w4 + 31 - __clz(occ4));
            ymn = min(ymn, h);
            ymx = max(ymx, h);
        }
    }

    #pragma unroll
    for (int off = 16; off; off >>= 1) {
        area += __shfl_down_sync(0xffffffffu, area, off);
        sx   += __shfl_down_sync(0xffffffffu, sx, off);
        sy   += __shfl_down_sync(0xffffffffu, sy, off);
        xmn = min(xmn, __shfl_down_sync(0xffffffffu, xmn, off));
        xmx = max(xmx, __shfl_down_sync(0xffffffffu, xmx, off));
        ymn = min(ymn, __shfl_down_sync(0xffffffffu, ymn, off));
        ymx = max(ymx, __shfl_down_sync(0xffffffffu, ymx, off));
    }
    __shared__ int red7[8][8];
    const int wid = tid >> 5, lid = tid & 31;
    if (lid == 0) {
        int* r = red7[wid];
        r[0] = area; r[1] = sx; r[2] = sy;
        r[3] = xmn; r[4] = xmx; r[5] = ymn; r[6] = ymx;
    }
    __syncthreads();
    // parallel final reduce: one thread per statistic (8 batched LDS each)
    if (tid < 7) {
        int acc = red7[0][tid];
        if (tid < 3) {
            #pragma unroll
            for (int i = 1; i < 8; i++) acc += red7[i][tid];
        } else if (tid == 3 || tid == 5) {
            #pragma unroll
            for (int i = 1; i < 8; i++) acc = min(acc, red7[i][tid]);
        } else {
            #pragma unroll
            for (int i = 1; i < 8; i++) acc = max(acc, red7[i][tid]);
        }
        g_stat25[chunk][bk][tid] = acc;
    }
}

// ============================================================
// Kernel 2: masked pooling via SMEM-staged fm tiles + 0/1 multipliers.
// grid = (4 d-chunks, 4 k-groups of 8, 8 b), 256 threads.
// ============================================================
__global__ __launch_bounds__(256) void k_pool(const float* __restrict__ fm) {
    const int dc  = blockIdx.x;
    const int kg  = blockIdx.y;
    const int b   = blockIdx.z;
    const int tid = threadIdx.x;
    const int d   = dc * 256 + tid;
    const int k0  = kg * 8;

    __shared__ alignas(16) float4 s_m[Nn][2];
    __shared__ alignas(16) float  s_f[24][256];
    __shared__ float s_inv[8];

    for (int n = tid; n < Nn; n += 256) {
        float mk[8];
        #pragma unroll
        for (int kk = 0; kk < 8; kk++) {
            unsigned word = g_bits[(b * Kk + k0 + kk) * 18 + (n >> 5)];
            mk[kk] = ((word >> (n & 31)) & 1u) ? 1.0f : 0.0f;
        }
        s_m[n][0] = make_float4(mk[0], mk[1], mk[2], mk[3]);
        s_m[n][1] = make_float4(mk[4], mk[5], mk[6], mk[7]);
    }
    if (tid < 8) {
        int c = g_cnt[b * Kk + k0 + tid];
        s_inv[tid] = (c > 0) ? (1.0f / (float)c) : 0.0f;
    }
    __syncthreads();

    float a0 = 0.f, a1 = 0.f, a2 = 0.f, a3 = 0.f;
    float a4 = 0.f, a5 = 0.f, a6 = 0.f, a7 = 0.f;
    const float* fb = fm + (size_t)b * Nn * Dd;
    const int r4 = tid >> 6, c4 = tid & 63;

    for (int n0 = 0; n0 < Nn; n0 += 24) {
        const float4* src = reinterpret_cast<const float4*>(fb + (size_t)n0 * Dd) + dc * 64;
        float4* dst = reinterpret_cast<float4*>(s_f);
        #pragma unroll
        for (int p = 0; p < 6; p++) {
            int r = r4 + p * 4;
            dst[r * 64 + c4] = src[(size_t)r * 256 + c4];
        }
        __syncthreads();
        #pragma unroll 8
        for (int r2 = 0; r2 < 24; r2++) {
            float f = s_f[r2][tid];
            float4 m0 = s_m[n0 + r2][0];
            float4 m1 = s_m[n0 + r2][1];
            a0 = fmaf(f, m0.x, a0); a1 = fmaf(f, m0.y, a1);
            a2 = fmaf(f, m0.z, a2); a3 = fmaf(f, m0.w, a3);
            a4 = fmaf(f, m1.x, a4); a5 = fmaf(f, m1.y, a5);
            a6 = fmaf(f, m1.z, a6); a7 = fmaf(f, m1.w, a7);
        }
        __syncthreads();
    }

    float* pp = g_x + (size_t)(b * Kk + k0) * XS + d;
    pp[0 * XS] = a0 * s_inv[0];
    pp[1 * XS] = a1 * s_inv[1];
    pp[2 * XS] = a2 * s_inv[2];
    pp[3 * XS] = a3 * s_inv[3];
    pp[4 * XS] = a4 * s_inv[4];
    pp[5 * XS] = a5 * s_inv[5];
    pp[6 * XS] = a6 * s_inv[6];
    pp[7 * XS] = a7 * s_inv[7];
}

// ============================================================
// Kernel 3a: layer1 partial GEMM over i=0..1087 (pooled+cls only).
// grid = (16 splits of 68, 32 row-groups of 8) = 512 blocks, 256 threads.
// ============================================================
__global__ __launch_bounds__(256) void k_mlp1(const float* __restrict__ W1) {
    const int split = blockIdx.x;
    const int rg    = blockIdx.y;
    const int j     = threadIdx.x;
    const int i0    = split * SLEN;

    __shared__ alignas(16) float xs[8][SLEN + 4];

    #pragma unroll
    for (int r = 0; r < 8; r++) {
        if (j < SLEN) xs[r][j] = g_x[(size_t)(rg * 8 + r) * XS + i0 + j];
    }
    __syncthreads();

    const float* wp = W1 + (size_t)i0 * OUTD + j;
    float a[8];
    #pragma unroll
    for (int r = 0; r < 8; r++) a[r] = 0.f;

    float w[8];
    #pragma unroll
    for (int u = 0; u < 8; u++) w[u] = wp[(size_t)u * OUTD];
    int t = 0;
    for (; t + 16 <= SLEN; t += 8) {
        float wn[8];
        #pragma unroll
        for (int u = 0; u < 8; u++) wn[u] = wp[(size_t)(t + 8 + u) * OUTD];
        #pragma unroll
        for (int r = 0; r < 8; r++) {
            float4 xa = *(const float4*)&xs[r][t];
            float4 xb = *(const float4*)&xs[r][t + 4];
            a[r] = fmaf(xa.x, w[0], a[r]); a[r] = fmaf(xa.y, w[1], a[r]);
            a[r] = fmaf(xa.z, w[2], a[r]); a[r] = fmaf(xa.w, w[3], a[r]);
            a[r] = fmaf(xb.x, w[4], a[r]); a[r] = fmaf(xb.y, w[5], a[r]);
            a[r] = fmaf(xb.z, w[6], a[r]); a[r] = fmaf(xb.w, w[7], a[r]);
        }
        #pragma unroll
        for (int u = 0; u < 8; u++) w[u] = wn[u];
    }
    {   // t = 56..63 (weights already in registers)
        #pragma unroll
        for (int r = 0; r < 8; r++) {
            float4 xa = *(const float4*)&xs[r][t];
            float4 xb = *(const float4*)&xs[r][t + 4];
            a[r] = fmaf(xa.x, w[0], a[r]); a[r] = fmaf(xa.y, w[1], a[r]);
            a[r] = fmaf(xa.z, w[2], a[r]); a[r] = fmaf(xa.w, w[3], a[r]);
            a[r] = fmaf(xb.x, w[4], a[r]); a[r] = fmaf(xb.y, w[5], a[r]);
            a[r] = fmaf(xb.z, w[6], a[r]); a[r] = fmaf(xb.w, w[7], a[r]);
        }
        t += 8;
    }
    for (; t < SLEN; t++) {   // 64..67
        float ws = wp[(size_t)t * OUTD];
        #pragma unroll
        for (int r = 0; r < 8; r++) a[r] = fmaf(xs[r][t], ws, a[r]);
    }

    float* gp = g_part + (size_t)(split * BK + rg * 8) * OUTD + j;
    #pragma unroll
    for (int r = 0; r < 8; r++) gp[(size_t)r * OUTD] = a[r];
}

// ============================================================
// Kernel 3b: combine 16 partials + inline geometry + bias + exact GELU +
// LayerNorm + layer2 with split-i halves (512 threads). Only post-join.
// ============================================================
__global__ __launch_bounds__(512) void k_mlp2(const float* __restrict__ b1,
                                              const float* __restrict__ ln_g,
                                              const float* __restrict__ ln_b,
                                              const float* __restrict__ W1,
                                              const float* __restrict__ W2,
                                              const float* __restrict__ b2,
                                              float* __restrict__ out) {
    const int row  = blockIdx.x;
    const int tid  = threadIdx.x;
    const int j    = tid & 255;
    const int half = tid >> 8;

    __shared__ alignas(16) float hn[OUTD];
    __shared__ float s_geo[5];
    __shared__ float red[2][8];
    __shared__ float mu_s, is_s;
    __shared__ float o_part[OUTD];

    // warp 0: reduce the 25 chunk-stat slots -> 5 geometry features
    if (tid < 32) {
        int A = 0, SX = 0, SY = 0, xm = 1 << 29, xM = -1, ym = 1 << 29, yM = -1;
        if (tid < NCHUNK) {
            const int* st = g_stat25[tid][row];
            A = st[0]; SX = st[1]; SY = st[2];
            xm = st[3]; xM = st[4]; ym = st[5]; yM = st[6];
        }
        #pragma unroll
        for (int off = 16; off; off >>= 1) {
            A  += __shfl_down_sync(0xffffffffu, A, off);
            SX += __shfl_down_sync(0xffffffffu, SX, off);
            SY += __shfl_down_sync(0xffffffffu, SY, off);
            xm = min(xm, __shfl_down_sync(0xffffffffu, xm, off));
            xM = max(xM, __shfl_down_sync(0xffffffffu, xM, off));
            ym = min(ym, __shfl_down_sync(0xffffffffu, ym, off));
            yM = max(yM, __shfl_down_sync(0xffffffffu, yM, off));
        }
        if (tid == 0) {
            float af = (float)A, safe = fmaxf(af, 1.0f);
            bool valid = (A >= 1);
            s_geo[0] = valid ? (float)SX / safe * (1.0f / Ww) : 0.0f;
            s_geo[1] = valid ? (float)SY / safe * (1.0f / Hh) : 0.0f;
            s_geo[2] = valid ? af * (1.0f / (Hh * Ww)) : 0.0f;
            s_geo[3] = valid ? (float)(xM - xm + 1) * (1.0f / Ww) : 0.0f;
            s_geo[4] = valid ? (float)(yM - ym + 1) * (1.0f / Hh) : 0.0f;
        }
    }

    float v = 0.f;
    if (half == 0) {
        v = b1[j];
        #pragma unroll
        for (int s = 0; s < NSPLIT; s++)
            v += g_part[(size_t)(s * BK + row) * OUTD + j];
    }
    __syncthreads();
    if (half == 0) {
        #pragma unroll
        for (int g = 0; g < 5; g++)
            v = fmaf(s_geo[g], W1[(size_t)(GEOM_I + g) * OUTD + j], v);
        v = 0.5f * v * (1.0f + erff(v * 0.7071067811865476f));
        float s1 = v, s2 = v * v;
        #pragma unroll
        for (int off = 16; off; off >>= 1) {
            s1 += __shfl_down_sync(0xffffffffu, s1, off);
            s2 += __shfl_down_sync(0xffffffffu, s2, off);
        }
        if ((j & 31) == 0) { red[0][j >> 5] = s1; red[1][j >> 5] = s2; }
    }
    __syncthreads();
    if (tid == 0) {
        float a = 0.f, b = 0.f;
        #pragma unroll
        for (int w = 0; w < 8; w++) { a += red[0][w]; b += red[1][w]; }
        float mu  = a * (1.0f / OUTD);
        float var = b * (1.0f / OUTD) - mu * mu;
        mu_s = mu;
        is_s = rsqrtf(var + 1e-5f);
    }
    __syncthreads();
    if (half == 0)
        hn[j] = (v - mu_s) * is_s * ln_g[j] + ln_b[j];
    __syncthreads();

    // layer2 split-i: each half does 128 of the 256 i's for column j
    const int ibase = half * 128;
    const float* wp = W2 + (size_t)ibase * OUTD + j;
    float o0 = (half == 0) ? b2[j] : 0.f, o1 = 0.f;
    float w[8];
    #pragma unroll
    for (int u = 0; u < 8; u++) w[u] = wp[(size_t)u * OUTD];
    int t = 0;
    for (; t + 16 <= 128; t += 8) {
        float wn[8];
        #pragma unroll
        for (int u = 0; u < 8; u++) wn[u] = wp[(size_t)(t + 8 + u) * OUTD];
        float4 ha = *(const float4*)&hn[ibase + t];
        float4 hb = *(const float4*)&hn[ibase + t + 4];
        o0 = fmaf(ha.x, w[0], o0); o1 = fmaf(ha.y, w[1], o1);
        o0 = fmaf(ha.z, w[2], o0); o1 = fmaf(ha.w, w[3], o1);
        o0 = fmaf(hb.x, w[4], o0); o1 = fmaf(hb.y, w[5], o1);
        o0 = fmaf(hb.z, w[6], o0); o1 = fmaf(hb.w, w[7], o1);
        #pragma unroll
        for (int u = 0; u < 8; u++) w[u] = wn[u];
    }
    {   // final 8 (weights in registers)
        float4 ha = *(const float4*)&hn[ibase + t];
        float4 hb = *(const float4*)&hn[ibase + t + 4];
        o0 = fmaf(ha.x, w[0], o0); o1 = fmaf(ha.y, w[1], o1);
        o0 = fmaf(ha.z, w[2], o0); o1 = fmaf(ha.w, w[3], o1);
        o0 = fmaf(hb.x, w[4], o0); o1 = fmaf(hb.y, w[5], o1);
        o0 = fmaf(hb.z, w[6], o0); o1 = fmaf(hb.w, w[7], o1);
    }
    if (half == 1) o_part[j] = o0 + o1;
    __syncthreads();
    if (half == 0)
        out[(size_t)row * OUTD + j] = o0 + o1 + o_part[j];
}

// ============================================================
extern "C" void kernel_launch(void* const* d_in, const int* in_sizes, int n_in,
                              void* d_out, int out_size) {
    const float* fm    = (const float*)d_in[0];
    const int*   masks = (const int*)d_in[1];
    const void*  cls   = d_in[2];
    const float* emb   = (const float*)d_in[3];
    const float* W1    = (const float*)d_in[4];
    const float* b1    = (const float*)d_in[5];
    const float* lg    = (const float*)d_in[6];
    const float* lb    = (const float*)d_in[7];
    const float* W2    = (const float*)d_in[8];
    const float* b2    = (const float*)d_in[9];
    float* out = (float*)d_out;

    // Fork-join: k_mask (DRAM-bound) on s1 overlaps init+pool+ALL of mlp1.
    cudaStream_t s1 = 0;
    cudaEvent_t  e0 = 0, e1 = 0;
    bool forked =
        (cudaStreamCreateWithFlags(&s1, cudaStreamNonBlocking) == cudaSuccess) &&
        (cudaEventCreateWithFlags(&e0, cudaEventDisableTiming) == cudaSuccess) &&
        (cudaEventCreateWithFlags(&e1, cudaEventDisableTiming) == cudaSuccess);

    if (forked) {
        cudaEventRecord(e0, 0);
        cudaStreamWaitEvent(s1, e0, 0);
        k_mask<<<dim3(NCHUNK, BK), 256, 0, s1>>>(masks);
        cudaEventRecord(e1, s1);

        k_init<<<BK, 576>>>(masks, cls, emb);
        k_pool<<<dim3(4, 4, 8), 256>>>(fm);
        k_mlp1<<<dim3(NSPLIT, 32), 256>>>(W1);

        cudaStreamWaitEvent(0, e1, 0);       // join: only mlp2 needs mask stats
        k_mlp2<<<BK, 512>>>(b1, lg, lb, W1, W2, b2, out);
    } else {
        k_init<<<BK, 576>>>(masks, cls, emb);
        k_mask<<<dim3(NCHUNK, BK), 256>>>(masks);
        k_pool<<<dim3(4, 4, 8), 256>>>(fm);
        k_mlp1<<<dim3(NSPLIT, 32), 256>>>(W1);
        k_mlp2<<<BK, 512>>>(b1, lg, lb, W1, W2, b2, out);
    }

    if (e0) cudaEventDestroy(e0);
    if (e1) cudaEventDestroy(e1);
    if (s1) cudaStreamDestroy(s1);
}

// round 17
// speedup vs baseline: 2.0994x; 1.0160x over previous
#include <cuda_runtime.h>
#include <cuda_bf16.h>
#include <math.h>

#define Kk 32
#define Hh 480
#define Ww 480
#define Nn 576
#define Dd 1024
#define CLSD 64
#define OUTD 256
#define INDIM 1093
#define BK 256
#define XS 1096      // padded row stride of assembled x (pooled-A + cls)
#define NSPLIT 16
#define SLEN 68      // 16*68 = 1088 = Dd+CLSD exactly; geom handled in mlp2
#define GEOM_I 1088  // Dd + CLSD
#define NCHUNK 25    // k_mask chunks per image (2304 int4 each)
#define CHUNK_I4 2304

// ---- scratch (static device globals: allocation-free) ----
__device__ int      g_stat25[NCHUNK][BK][8]; // per-chunk partial stats
__device__ int      g_done[BK];              // per-bk mask completion counters
__device__ unsigned g_bits[BK * 18];         // 576-bit sample mask per (b,k)
__device__ int      g_cnt[BK];
__device__ float    g_x[BK * XS];            // pooled half A + cls
__device__ float    g_xB[BK * Dd];           // pooled half B
__device__ float    g_part[NSPLIT * BK * OUTD];
__device__ float    g_hpre[BK * OUTD];       // b1 + sum of 16 partials
__device__ float    g_warm[16384];           // W2 L2-warm sink (never read)

// ============================================================
// Kernel Z: zero per-bk completion counters (on mask stream, before k_mask).
// ============================================================
__global__ void k_zero() { g_done[threadIdx.x] = 0; }

// ============================================================
// Kernel 0: sample bits + class-embedding gather (the ONE scattered pass).
// ============================================================
__global__ __launch_bounds__(576) void k_init(const int* __restrict__ masks,
                                              const void* __restrict__ cls_raw,
                                              const float* __restrict__ emb) {
    const int bk  = blockIdx.x;
    const int tid = threadIdx.x;
    const int wid = tid >> 5, lid = tid & 31;
    __shared__ int s_flag, s_cnt;
    if (tid == 0) { s_flag = 0; s_cnt = 0; }
    __syncthreads();
    if (tid < 128) {
        if (((const int*)cls_raw)[2 * tid + 1] != 0) atomicOr(&s_flag, 1);
    }
    const int* mb = masks + (size_t)bk * (Hh * Ww);
    int i = tid / 24, j = tid - i * 24;
    int on = mb[(20 * i) * Ww + 20 * j] > 0;
    unsigned bal = __ballot_sync(0xffffffffu, on);
    if (lid == 0) { g_bits[bk * 18 + wid] = bal; atomicAdd(&s_cnt, __popc(bal)); }
    __syncthreads();
    if (tid == 0) g_cnt[bk] = s_cnt;
    const bool is64 = (s_flag == 0);
    int c = is64 ? (int)((const long long*)cls_raw)[bk]
                 : ((const int*)cls_raw)[bk];
    if (tid < CLSD) g_x[(size_t)bk * XS + Dd + tid] = emb[c * CLSD + tid];
}

// ============================================================
// Kernel 1: full-res mask stats (R16 v3) + per-bk completion signal.
// grid = (25 chunks, 256 bk), 256 threads, 9 streaming int4/thread.
// ============================================================
__global__ __launch_bounds__(256) void k_mask(const int* __restrict__ masks) {
    const int chunk = blockIdx.x;
    const int bk    = blockIdx.y;
    const int tid   = threadIdx.x;
    const int4* mp  = reinterpret_cast<const int4*>(masks + (size_t)bk * (Hh * Ww));
    const int base  = chunk * CHUNK_I4 + tid;

    int4 v[9];
    #pragma unroll
    for (int u = 0; u < 9; u++)
        v[u] = __ldcs(&mp[base + u * 256]);

    int area = 0, sx = 0, sy = 0;
    int xmn = 1 << 29, xmx = -1, ymn = 1 << 29, ymx = -1;
    #pragma unroll
    for (int u = 0; u < 9; u++) {
        const int gidx = base + u * 256;
        const int h    = gidx / 120;
        const int w4   = (gidx - h * 120) * 4;
        int c = v[u].x + v[u].y + v[u].z + v[u].w;
        area += c;
        sy   += h * c;
        sx   += w4 * c + v[u].y + 2 * v[u].z + 3 * v[u].w;
        int occ4 = v[u].x + 2 * v[u].y + 4 * v[u].z + 8 * v[u].w;
        if (occ4) {
            xmn = min(xmn, w4 + __ffs(occ4) - 1);
            xmx = max(xmx, w4 + 31 - __clz(occ4));
            ymn = min(ymn, h);
            ymx = max(ymx, h);
        }
    }

    #pragma unroll
    for (int off = 16; off; off >>= 1) {
        area += __shfl_down_sync(0xffffffffu, area, off);
        sx   += __shfl_down_sync(0xffffffffu, sx, off);
        sy   += __shfl_down_sync(0xffffffffu, sy, off);
        xmn = min(xmn, __shfl_down_sync(0xffffffffu, xmn, off));
        xmx = max(xmx, __shfl_down_sync(0xffffffffu, xmx, off));
        ymn = min(ymn, __shfl_down_sync(0xffffffffu, ymn, off));
        ymx = max(ymx, __shfl_down_sync(0xffffffffu, ymx, off));
    }
    __shared__ int red7[8][8];
    const int wid = tid >> 5, lid = tid & 31;
    if (lid == 0) {
        int* r = red7[wid];
        r[0] = area; r[1] = sx; r[2] = sy;
        r[3] = xmn; r[4] = xmx; r[5] = ymn; r[6] = ymx;
    }
    __syncthreads();
    if (tid < 7) {
        int acc = red7[0][tid];
        if (tid < 3) {
            #pragma unroll
            for (int i = 1; i < 8; i++) acc += red7[i][tid];
        } else if (tid == 3 || tid == 5) {
            #pragma unroll
            for (int i = 1; i < 8; i++) acc = min(acc, red7[i][tid]);
        } else {
            #pragma unroll
            for (int i = 1; i < 8; i++) acc = max(acc, red7[i][tid]);
        }
        g_stat25[chunk][bk][tid] = acc;
        __threadfence();
    }
    __syncthreads();
    if (tid == 0) atomicAdd(&g_done[bk], 1);   // release: after fence+sync
}

// ============================================================
// Kernel 2: masked pooling, n-split halves. grid = (4 dc, 4 kg, 16 z)
// where z = b*2 + nhalf. Half A -> g_x, half B -> g_xB (summed in mlp1).
// ============================================================
__global__ __launch_bounds__(256) void k_pool(const float* __restrict__ fm) {
    const int dc  = blockIdx.x;
    const int kg  = blockIdx.y;
    const int b   = blockIdx.z >> 1;
    const int nh  = blockIdx.z & 1;
    const int tid = threadIdx.x;
    const int d   = dc * 256 + tid;
    const int k0  = kg * 8;
    const int n0g = nh * 288;

    __shared__ alignas(16) float4 s_m[288][2];
    __shared__ alignas(16) float  s_f[24][256];
    __shared__ float s_inv[8];

    for (int n = tid; n < 288; n += 256) {
        const int na = n0g + n;
        float mk[8];
        #pragma unroll
        for (int kk = 0; kk < 8; kk++) {
            unsigned word = g_bits[(b * Kk + k0 + kk) * 18 + (na >> 5)];
            mk[kk] = ((word >> (na & 31)) & 1u) ? 1.0f : 0.0f;
        }
        s_m[n][0] = make_float4(mk[0], mk[1], mk[2], mk[3]);
        s_m[n][1] = make_float4(mk[4], mk[5], mk[6], mk[7]);
    }
    if (tid < 8) {
        int c = g_cnt[b * Kk + k0 + tid];
        s_inv[tid] = (c > 0) ? (1.0f / (float)c) : 0.0f;
    }
    __syncthreads();

    float a0 = 0.f, a1 = 0.f, a2 = 0.f, a3 = 0.f;
    float a4 = 0.f, a5 = 0.f, a6 = 0.f, a7 = 0.f;
    const float* fb = fm + (size_t)b * Nn * Dd;
    const int r4 = tid >> 6, c4 = tid & 63;

    for (int n0 = 0; n0 < 288; n0 += 24) {
        const float4* src = reinterpret_cast<const float4*>(fb + (size_t)(n0g + n0) * Dd) + dc * 64;
        float4* dst = reinterpret_cast<float4*>(s_f);
        #pragma unroll
        for (int p = 0; p < 6; p++) {
            int r = r4 + p * 4;
            dst[r * 64 + c4] = src[(size_t)r * 256 + c4];
        }
        __syncthreads();
        #pragma unroll 8
        for (int r2 = 0; r2 < 24; r2++) {
            float f = s_f[r2][tid];
            float4 m0 = s_m[n0 + r2][0];
            float4 m1 = s_m[n0 + r2][1];
            a0 = fmaf(f, m0.x, a0); a1 = fmaf(f, m0.y, a1);
            a2 = fmaf(f, m0.z, a2); a3 = fmaf(f, m0.w, a3);
            a4 = fmaf(f, m1.x, a4); a5 = fmaf(f, m1.y, a5);
            a6 = fmaf(f, m1.z, a6); a7 = fmaf(f, m1.w, a7);
        }
        __syncthreads();
    }

    if (nh == 0) {
        float* pp = g_x + (size_t)(b * Kk + k0) * XS + d;
        pp[0 * XS] = a0 * s_inv[0]; pp[1 * XS] = a1 * s_inv[1];
        pp[2 * XS] = a2 * s_inv[2]; pp[3 * XS] = a3 * s_inv[3];
        pp[4 * XS] = a4 * s_inv[4]; pp[5 * XS] = a5 * s_inv[5];
        pp[6 * XS] = a6 * s_inv[6]; pp[7 * XS] = a7 * s_inv[7];
    } else {
        float* pp = g_xB + (size_t)(b * Kk + k0) * Dd + d;
        pp[0 * Dd] = a0 * s_inv[0]; pp[1 * Dd] = a1 * s_inv[1];
        pp[2 * Dd] = a2 * s_inv[2]; pp[3 * Dd] = a3 * s_inv[3];
        pp[4 * Dd] = a4 * s_inv[4]; pp[5 * Dd] = a5 * s_inv[5];
        pp[6 * Dd] = a6 * s_inv[6]; pp[7 * Dd] = a7 * s_inv[7];
    }
}

// ============================================================
// Kernel 3a: layer1 partial GEMM over i=0..1087 (x = halfA + halfB).
// grid = (16 splits of 68, 32 row-groups of 8), 256 threads.
// ============================================================
__global__ __launch_bounds__(256) void k_mlp1(const float* __restrict__ W1) {
    const int split = blockIdx.x;
    const int rg    = blockIdx.y;
    const int j     = threadIdx.x;
    const int i0    = split * SLEN;

    __shared__ alignas(16) float xs[8][SLEN + 4];

    #pragma unroll
    for (int r = 0; r < 8; r++) {
        if (j < SLEN) {
            const int row = rg * 8 + r, gi = i0 + j;
            float va = g_x[(size_t)row * XS + gi];
            float vb = (gi < Dd) ? g_xB[(size_t)row * Dd + gi] : 0.f;
            xs[r][j] = va + vb;
        }
    }
    __syncthreads();

    const float* wp = W1 + (size_t)i0 * OUTD + j;
    float a[8];
    #pragma unroll
    for (int r = 0; r < 8; r++) a[r] = 0.f;

    float w[8];
    #pragma unroll
    for (int u = 0; u < 8; u++) w[u] = wp[(size_t)u * OUTD];
    int t = 0;
    for (; t + 16 <= SLEN; t += 8) {
        float wn[8];
        #pragma unroll
        for (int u = 0; u < 8; u++) wn[u] = wp[(size_t)(t + 8 + u) * OUTD];
        #pragma unroll
        for (int r = 0; r < 8; r++) {
            float4 xa = *(const float4*)&xs[r][t];
            float4 xb = *(const float4*)&xs[r][t + 4];
            a[r] = fmaf(xa.x, w[0], a[r]); a[r] = fmaf(xa.y, w[1], a[r]);
            a[r] = fmaf(xa.z, w[2], a[r]); a[r] = fmaf(xa.w, w[3], a[r]);
            a[r] = fmaf(xb.x, w[4], a[r]); a[r] = fmaf(xb.y, w[5], a[r]);
            a[r] = fmaf(xb.z, w[6], a[r]); a[r] = fmaf(xb.w, w[7], a[r]);
        }
        #pragma unroll
        for (int u = 0; u < 8; u++) w[u] = wn[u];
    }
    {
        #pragma unroll
        for (int r = 0; r < 8; r++) {
            float4 xa = *(const float4*)&xs[r][t];
            float4 xb = *(const float4*)&xs[r][t + 4];
            a[r] = fmaf(xa.x, w[0], a[r]); a[r] = fmaf(xa.y, w[1], a[r]);
            a[r] = fmaf(xa.z, w[2], a[r]); a[r] = fmaf(xa.w, w[3], a[r]);
            a[r] = fmaf(xb.x, w[4], a[r]); a[r] = fmaf(xb.y, w[5], a[r]);
            a[r] = fmaf(xb.z, w[6], a[r]); a[r] = fmaf(xb.w, w[7], a[r]);
        }
        t += 8;
    }
    for (; t < SLEN; t++) {
        float ws = wp[(size_t)t * OUTD];
        #pragma unroll
        for (int r = 0; r < 8; r++) a[r] = fmaf(xs[r][t], ws, a[r]);
    }

    float* gp = g_part + (size_t)(split * BK + rg * 8) * OUTD + j;
    #pragma unroll
    for (int r = 0; r < 8; r++) gp[(size_t)r * OUTD] = a[r];
}

// ============================================================
// Kernel 3b-pre: combine 16 partials + b1 -> g_hpre; warm W2 into L2.
// grid = 256 blocks, 256 threads. Pre-join (hidden under mask).
// ============================================================
__global__ __launch_bounds__(256) void k_comb(const float* __restrict__ b1,
                                              const float* __restrict__ W2) {
    const int row = blockIdx.x;
    const int j   = threadIdx.x;
    float v = b1[j];
    #pragma unroll
    for (int s = 0; s < NSPLIT; s++)
        v += g_part[(size_t)(s * BK + row) * OUTD + j];
    g_hpre[(size_t)row * OUTD + j] = v;
    // L2-warm W2 (65536 floats = 16384 float4; one per global thread)
    const int gid = row * 256 + j;
    if (gid < 16384) {
        float4 w = reinterpret_cast<const float4*>(W2)[gid];
        g_warm[gid] = w.x + w.y + w.z + w.w;
    }
}

// ============================================================
// Kernel 3b: per-row spin-wait on mask completion + geometry + GELU +
// LayerNorm + layer2 (split-i halves, 512 threads). NO graph join needed.
// ============================================================
__global__ __launch_bounds__(512) void k_mlp2(const float* __restrict__ ln_g,
                                              const float* __restrict__ ln_b,
                                              const float* __restrict__ W1,
                                              const float* __restrict__ W2,
                                              const float* __restrict__ b2,
                                              float* __restrict__ out) {
    const int row  = blockIdx.x;
    const int tid  = threadIdx.x;
    const int j    = tid & 255;
    const int half = tid >> 8;

    __shared__ alignas(16) float hn[OUTD];
    __shared__ float s_geo[5];
    __shared__ float red[2][8];
    __shared__ float mu_s, is_s;
    __shared__ float o_part[OUTD];

    // pre-load (depends only on k_comb, already ordered on this stream)
    float v = (half == 0) ? g_hpre[(size_t)row * OUTD + j] : 0.f;

    // spin until this row's 25 mask chunks have landed
    if (tid == 0) {
        while (*((volatile int*)&g_done[row]) < NCHUNK) __nanosleep(200);
        __threadfence();
    }
    __syncthreads();

    // warp 0: reduce 25 chunk-stat slots -> 5 geometry features
    if (tid < 32) {
        int A = 0, SX = 0, SY = 0, xm = 1 << 29, xM = -1, ym = 1 << 29, yM = -1;
        if (tid < NCHUNK) {
            const int* st = g_stat25[tid][row];
            A = st[0]; SX = st[1]; SY = st[2];
            xm = st[3]; xM = st[4]; ym = st[5]; yM = st[6];
        }
        #pragma unroll
        for (int off = 16; off; off >>= 1) {
            A  += __shfl_down_sync(0xffffffffu, A, off);
            SX += __shfl_down_sync(0xffffffffu, SX, off);
            SY += __shfl_down_sync(0xffffffffu, SY, off);
            xm = min(xm, __shfl_down_sync(0xffffffffu, xm, off));
            xM = max(xM, __shfl_down_sync(0xffffffffu, xM, off));
            ym = min(ym, __shfl_down_sync(0xffffffffu, ym, off));
            yM = max(yM, __shfl_down_sync(0xffffffffu, yM, off));
        }
        if (tid == 0) {
            float af = (float)A, safe = fmaxf(af, 1.0f);
            bool valid = (A >= 1);
            s_geo[0] = valid ? (float)SX / safe * (1.0f / Ww) : 0.0f;
            s_geo[1] = valid ? (float)SY / safe * (1.0f / Hh) : 0.0f;
            s_geo[2] = valid ? af * (1.0f / (Hh * Ww)) : 0.0f;
            s_geo[3] = valid ? (float)(xM - xm + 1) * (1.0f / Ww) : 0.0f;
            s_geo[4] = valid ? (float)(yM - ym + 1) * (1.0f / Hh) : 0.0f;
        }
    }
    __syncthreads();

    if (half == 0) {
        #pragma unroll
        for (int g = 0; g < 5; g++)
            v = fmaf(s_geo[g], W1[(size_t)(GEOM_I + g) * OUTD + j], v);
        v = 0.5f * v * (1.0f + erff(v * 0.7071067811865476f));
        float s1 = v, s2 = v * v;
        #pragma unroll
        for (int off = 16; off; off >>= 1) {
            s1 += __shfl_down_sync(0xffffffffu, s1, off);
            s2 += __shfl_down_sync(0xffffffffu, s2, off);
        }
        if ((j & 31) == 0) { red[0][j >> 5] = s1; red[1][j >> 5] = s2; }
    }
    __syncthreads();
    if (tid == 0) {
        float a = 0.f, b = 0.f;
        #pragma unroll
        for (int w = 0; w < 8; w++) { a += red[0][w]; b += red[1][w]; }
        float mu  = a * (1.0f / OUTD);
        float var = b * (1.0f / OUTD) - mu * mu;
        mu_s = mu;
        is_s = rsqrtf(var + 1e-5f);
    }
    __syncthreads();
    if (half == 0)
        hn[j] = (v - mu_s) * is_s * ln_g[j] + ln_b[j];
    __syncthreads();

    const int ibase = half * 128;
    const float* wp = W2 + (size_t)ibase * OUTD + j;
    float o0 = (half == 0) ? b2[j] : 0.f, o1 = 0.f;
    float w[8];
    #pragma unroll
    for (int u = 0; u < 8; u++) w[u] = wp[(size_t)u * OUTD];
    int t = 0;
    for (; t + 16 <= 128; t += 8) {
        float wn[8];
        #pragma unroll
        for (int u = 0; u < 8; u++) wn[u] = wp[(size_t)(t + 8 + u) * OUTD];
        float4 ha = *(const float4*)&hn[ibase + t];
        float4 hb = *(const float4*)&hn[ibase + t + 4];
        o0 = fmaf(ha.x, w[0], o0); o1 = fmaf(ha.y, w[1], o1);
        o0 = fmaf(ha.z, w[2], o0); o1 = fmaf(ha.w, w[3], o1);
        o0 = fmaf(hb.x, w[4], o0); o1 = fmaf(hb.y, w[5], o1);
        o0 = fmaf(hb.z, w[6], o0); o1 = fmaf(hb.w, w[7], o1);
        #pragma unroll
        for (int u = 0; u < 8; u++) w[u] = wn[u];
    }
    {
        float4 ha = *(const float4*)&hn[ibase + t];
        float4 hb = *(const float4*)&hn[ibase + t + 4];
        o0 = fmaf(ha.x, w[0], o0); o1 = fmaf(ha.y, w[1], o1);
        o0 = fmaf(ha.z, w[2], o0); o1 = fmaf(ha.w, w[3], o1);
        o0 = fmaf(hb.x, w[4], o0); o1 = fmaf(hb.y, w[5], o1);
        o0 = fmaf(hb.z, w[6], o0); o1 = fmaf(hb.w, w[7], o1);
    }
    if (half == 1) o_part[j] = o0 + o1;
    __syncthreads();
    if (half == 0)
        out[(size_t)row * OUTD + j] = o0 + o1 + o_part[j];
}

// ============================================================
extern "C" void kernel_launch(void* const* d_in, const int* in_sizes, int n_in,
                              void* d_out, int out_size) {
    const float* fm    = (const float*)d_in[0];
    const int*   masks = (const int*)d_in[1];
    const void*  cls   = d_in[2];
    const float* emb   = (const float*)d_in[3];
    const float* W1    = (const float*)d_in[4];
    const float* b1    = (const float*)d_in[5];
    const float* lg    = (const float*)d_in[6];
    const float* lb    = (const float*)d_in[7];
    const float* W2    = (const float*)d_in[8];
    const float* b2    = (const float*)d_in[9];
    float* out = (float*)d_out;

    cudaStream_t s1 = 0;
    cudaEvent_t  e0 = 0, e1 = 0;
    bool forked =
        (cudaStreamCreateWithFlags(&s1, cudaStreamNonBlocking) == cudaSuccess) &&
        (cudaEventCreateWithFlags(&e0, cudaEventDisableTiming) == cudaSuccess) &&
        (cudaEventCreateWithFlags(&e1, cudaEventDisableTiming) == cudaSuccess);

    if (forked) {
        cudaEventRecord(e0, 0);
        cudaStreamWaitEvent(s1, e0, 0);
        k_zero<<<1, BK, 0, s1>>>();
        k_mask<<<dim3(NCHUNK, BK), 256, 0, s1>>>(masks);
        cudaEventRecord(e1, s1);

        k_init<<<BK, 576>>>(masks, cls, emb);
        k_pool<<<dim3(4, 4, 16), 256>>>(fm);
        k_mlp1<<<dim3(NSPLIT, 32), 256>>>(W1);
        k_comb<<<BK, 256>>>(b1, W2);
        k_mlp2<<<BK, 512>>>(lg, lb, W1, W2, b2, out);   // spin-syncs on g_done

        cudaStreamWaitEvent(0, e1, 0);   // join s1 for capture legality only
    } else {
        k_zero<<<1, BK>>>();
        k_mask<<<dim3(NCHUNK, BK), 256>>>(masks);
        k_init<<<BK, 576>>>(masks, cls, emb);
        k_pool<<<dim3(4, 4, 16), 256>>>(fm);
        k_mlp1<<<dim3(NSPLIT, 32), 256>>>(W1);
        k_comb<<<BK, 256>>>(b1, W2);
        k_mlp2<<<BK, 512>>>(lg, lb, W1, W2, b2, out);
    }

    if (e0) cudaEventDestroy(e0);
    if (e1) cudaEventDestroy(e1);
    if (s1) cudaStreamDestroy(s1);
}